// round 15
// baseline (speedup 1.0000x reference)
#include <cuda_runtime.h>
#include <cuda_fp16.h>
#include <cstdint>

// ---------------- problem constants ----------------
#define NMAX   50000
#define NPAD   50048
#define EMAX   800000
#define FH     128
#define NHID   512
#define NOUT   256
#define SCAN_B 256

// ---------------- device scratch (no allocs allowed) --------------
__device__ __half g_hWh[(size_t)NPAD * FH];
__device__ float  g_c  [(size_t)NPAD * FH];
__device__ float  g_dis[NMAX];
__device__ int    g_cnt [NMAX];
__device__ int    g_off [NMAX + 1];
__device__ int    g_fill[NMAX];
__device__ int    g_part[SCAN_B];
__device__ int2   g_edge[EMAX];              // packed (src, __float_as_int(norm))
__device__ float  g_pool[NOUT * FH];
__device__ float  g_m1  [NOUT * NHID];
__device__ int    g_bar_cnt[2];
__device__ int    g_bar_flag[2];

// ---------------- grid barrier (196 blocks, all resident; flags memset) ---
__device__ __forceinline__ void grid_bar(int i) {
    __syncthreads();
    if (threadIdx.x == 0) {
        __threadfence();
        int old = atomicAdd(&g_bar_cnt[i], 1);
        if (old == (int)gridDim.x - 1) {
            *(volatile int*)&g_bar_flag[i] = 1;
            __threadfence();
        } else {
            while (*(volatile int*)&g_bar_flag[i] == 0) {}
            __threadfence();
        }
    }
    __syncthreads();
}

// ---------------- fused prep: count -> dis -> exclusive scan --------------
__global__ void k_prep(const int* __restrict__ ei, int E, int M) {
    int stride4 = gridDim.x * blockDim.x * 4;
    for (int base = (blockIdx.x * blockDim.x + threadIdx.x) * 4;
         base < E; base += stride4) {
        if (base + 3 < E) {
            int4 d4 = *(const int4*)(ei + E + base);
            atomicAdd(&g_cnt[d4.x], 1);
            atomicAdd(&g_cnt[d4.y], 1);
            atomicAdd(&g_cnt[d4.z], 1);
            atomicAdd(&g_cnt[d4.w], 1);
        } else {
            for (int e = base; e < E; e++) atomicAdd(&g_cnt[ei[E + e]], 1);
        }
    }
    grid_bar(0);

    __shared__ int sm[SCAN_B];
    int t = threadIdx.x, bid = blockIdx.x;
    int i = bid * SCAN_B + t;
    int v = (i < M) ? g_cnt[i] : 0;
    if (i < M) g_dis[i] = rsqrtf((float)(v + 1));     // +1 self loop
    sm[t] = v;
    __syncthreads();
    for (int d = SCAN_B / 2; d > 0; d >>= 1) {
        if (t < d) sm[t] += sm[t + d];
        __syncthreads();
    }
    if (t == 0) g_part[bid] = sm[0];
    grid_bar(1);

    int nb = (int)gridDim.x;
    int pv = (t < nb) ? g_part[t] : 0;
    sm[t] = pv;
    __syncthreads();
    for (int d = 1; d < SCAN_B; d <<= 1) {
        int add = (t >= d) ? sm[t - d] : 0;
        __syncthreads();
        sm[t] += add;
        __syncthreads();
    }
    int base  = sm[bid] - g_part[bid];
    int total = sm[SCAN_B - 1];
    __syncthreads();
    sm[t] = v;
    __syncthreads();
    for (int d = 1; d < SCAN_B; d <<= 1) {
        int add = (t >= d) ? sm[t - d] : 0;
        __syncthreads();
        sm[t] += add;
        __syncthreads();
    }
    if (i < M) {
        int ex = base + sm[t] - v;
        g_off[i]  = ex;
        g_fill[i] = ex;
    }
    if (bid == 0 && t == 0) g_off[M] = total;
}

// 2 edges/thread (1563 blocks)
__global__ void k_fill(const int* __restrict__ ei, int E) {
    int base = (blockIdx.x * blockDim.x + threadIdx.x) * 2;
    if (base + 1 < E) {
        int2 s2 = *(const int2*)(ei + base);
        int2 d2 = *(const int2*)(ei + E + base);
        float ds0 = g_dis[s2.x], dd0 = g_dis[d2.x];
        float ds1 = g_dis[s2.y], dd1 = g_dis[d2.y];
        int p0 = atomicAdd(&g_fill[d2.x], 1);
        int p1 = atomicAdd(&g_fill[d2.y], 1);
        g_edge[p0] = make_int2(s2.x, __float_as_int(ds0 * dd0));
        g_edge[p1] = make_int2(s2.y, __float_as_int(ds1 * dd1));
    } else if (base < E) {
        int s = ei[base];
        int d = ei[E + base];
        int p = atomicAdd(&g_fill[d], 1);
        g_edge[p] = make_int2(s, __float_as_int(g_dis[s] * g_dis[d]));
    }
}

// ---------------- tensor-core node GEMM: g_hWh = half(act(A) @ W) ---------
template <int K, bool FROM_C>
__global__ void __launch_bounds__(256, 2)
k_gemm_t(const float* __restrict__ X, const float* __restrict__ W,
         const float* __restrict__ bias, int M) {
    extern __shared__ __half sh[];
    const int LDA = K + 8;
    __half* As = sh;                    // [128][LDA]
    __half* Bs = sh + 128 * LDA;        // [128][LDA]  (Bs[n][k] = W[k][n])
    int t  = threadIdx.x;
    int m0 = blockIdx.x * 128;
    const float* A = FROM_C ? g_c : X;

    {
        const float4* W4 = (const float4*)W;
        for (int i = t; i < K * 32; i += 256) {
            int k  = i >> 5;
            int n4 = (i & 31) << 2;
            float4 w = W4[i];
            Bs[(n4 + 0) * LDA + k] = __float2half(w.x);
            Bs[(n4 + 1) * LDA + k] = __float2half(w.y);
            Bs[(n4 + 2) * LDA + k] = __float2half(w.z);
            Bs[(n4 + 3) * LDA + k] = __float2half(w.w);
        }
    }
    {
        const int rw = K / 8;
        for (int i = t; i < 128 * rw; i += 256) {
            int r  = i / rw;
            int c8 = (i - r * rw) * 8;
            int row = m0 + r;
            float4 v0 = make_float4(0.f, 0.f, 0.f, 0.f), v1 = v0;
            if (row < M) {
                v0 = *(const float4*)(A + (size_t)row * K + c8);
                v1 = *(const float4*)(A + (size_t)row * K + c8 + 4);
            }
            if (FROM_C) {
                float4 ba = ((const float4*)bias)[c8 >> 2];
                float4 bb = ((const float4*)bias)[(c8 >> 2) + 1];
                v0.x = fmaxf(v0.x + ba.x, 0.f); v0.y = fmaxf(v0.y + ba.y, 0.f);
                v0.z = fmaxf(v0.z + ba.z, 0.f); v0.w = fmaxf(v0.w + ba.w, 0.f);
                v1.x = fmaxf(v1.x + bb.x, 0.f); v1.y = fmaxf(v1.y + bb.y, 0.f);
                v1.z = fmaxf(v1.z + bb.z, 0.f); v1.w = fmaxf(v1.w + bb.w, 0.f);
            }
            __half2 h0 = __floats2half2_rn(v0.x, v0.y);
            __half2 h1 = __floats2half2_rn(v0.z, v0.w);
            __half2 h2 = __floats2half2_rn(v1.x, v1.y);
            __half2 h3 = __floats2half2_rn(v1.z, v1.w);
            uint4 pk = make_uint4(*(unsigned*)&h0, *(unsigned*)&h1,
                                  *(unsigned*)&h2, *(unsigned*)&h3);
            *(uint4*)(As + r * LDA + c8) = pk;
        }
    }
    __syncthreads();

    int lane = t & 31;
    int wid  = t >> 5;
    int wm = wid & 3;
    int wn = wid >> 2;
    int g  = lane >> 2;
    int tg = lane & 3;

    float c[2][8][4];
    #pragma unroll
    for (int mi = 0; mi < 2; mi++)
        #pragma unroll
        for (int ni = 0; ni < 8; ni++)
            #pragma unroll
            for (int q = 0; q < 4; q++) c[mi][ni][q] = 0.f;

    #pragma unroll
    for (int k0 = 0; k0 < K; k0 += 16) {
        uint32_t a[2][4], b[8][2];
        #pragma unroll
        for (int mi = 0; mi < 2; mi++) {
            int r = wm * 32 + mi * 16 + g;
            const __half* p = As + r * LDA + k0 + tg * 2;
            a[mi][0] = *(const uint32_t*)p;
            a[mi][1] = *(const uint32_t*)(p + 8 * LDA);
            a[mi][2] = *(const uint32_t*)(p + 8);
            a[mi][3] = *(const uint32_t*)(p + 8 * LDA + 8);
        }
        #pragma unroll
        for (int ni = 0; ni < 8; ni++) {
            int n = wn * 64 + ni * 8 + g;
            const __half* p = Bs + n * LDA + k0 + tg * 2;
            b[ni][0] = *(const uint32_t*)p;
            b[ni][1] = *(const uint32_t*)(p + 8);
        }
        #pragma unroll
        for (int mi = 0; mi < 2; mi++)
            #pragma unroll
            for (int ni = 0; ni < 8; ni++)
                asm volatile(
                    "mma.sync.aligned.m16n8k16.row.col.f32.f16.f16.f32 "
                    "{%0,%1,%2,%3}, {%4,%5,%6,%7}, {%8,%9}, {%0,%1,%2,%3};"
                    : "+f"(c[mi][ni][0]), "+f"(c[mi][ni][1]),
                      "+f"(c[mi][ni][2]), "+f"(c[mi][ni][3])
                    : "r"(a[mi][0]), "r"(a[mi][1]), "r"(a[mi][2]), "r"(a[mi][3]),
                      "r"(b[ni][0]), "r"(b[ni][1]));
    }

    #pragma unroll
    for (int mi = 0; mi < 2; mi++) {
        int r0 = m0 + wm * 32 + mi * 16 + g;
        #pragma unroll
        for (int ni = 0; ni < 8; ni++) {
            int col = wn * 64 + ni * 8 + tg * 2;
            __half2 lo = __floats2half2_rn(c[mi][ni][0], c[mi][ni][1]);
            __half2 hi = __floats2half2_rn(c[mi][ni][2], c[mi][ni][3]);
            *(__half2*)(g_hWh + (size_t)r0 * FH + col)        = lo;
            *(__half2*)(g_hWh + (size_t)(r0 + 8) * FH + col)  = hi;
        }
    }
}

// ---------------- conv: g_c[dst] = sum_e norm_e * half(g_hWh[src]) --------
__device__ __forceinline__ float4 ld_h4(const __half* p) {
    uint2 u = *(const uint2*)p;
    __half2 a = *(__half2*)&u.x;
    __half2 b = *(__half2*)&u.y;
    float2 fa = __half22float2(a);
    float2 fb = __half22float2(b);
    return make_float4(fa.x, fa.y, fb.x, fb.y);
}

__global__ void __launch_bounds__(256, 7) k_conv(int M) {
    int warp = (blockIdx.x * blockDim.x + threadIdx.x) >> 5;
    if (warp >= M) return;
    int lane = threadIdx.x & 31;
    int node = warp;

    float d  = g_dis[node];
    float s0 = d * d;
    float4 h0 = ld_h4(g_hWh + (size_t)node * FH + lane * 4);
    float4 acc = make_float4(s0 * h0.x, s0 * h0.y, s0 * h0.z, s0 * h0.w);

    int e  = g_off[node];
    int e1 = g_off[node + 1];
    while (e < e1) {
        int n = e1 - e; if (n > 32) n = 32;
        int   idx = 0;
        float v   = 0.f;
        if (lane < n) {
            int2 pk = g_edge[e + lane];
            idx = pk.x; v = __int_as_float(pk.y);
        }
        int j = 0;
        for (; j + 4 <= n; j += 4) {
            int   sA = __shfl_sync(0xffffffffu, idx, j);
            int   sB = __shfl_sync(0xffffffffu, idx, j + 1);
            int   sC = __shfl_sync(0xffffffffu, idx, j + 2);
            int   sD = __shfl_sync(0xffffffffu, idx, j + 3);
            float vA = __shfl_sync(0xffffffffu, v, j);
            float vB = __shfl_sync(0xffffffffu, v, j + 1);
            float vC = __shfl_sync(0xffffffffu, v, j + 2);
            float vD = __shfl_sync(0xffffffffu, v, j + 3);
            float4 hA = ld_h4(g_hWh + (size_t)sA * FH + lane * 4);
            float4 hB = ld_h4(g_hWh + (size_t)sB * FH + lane * 4);
            float4 hC = ld_h4(g_hWh + (size_t)sC * FH + lane * 4);
            float4 hD = ld_h4(g_hWh + (size_t)sD * FH + lane * 4);
            acc.x = fmaf(vA, hA.x, acc.x); acc.y = fmaf(vA, hA.y, acc.y);
            acc.z = fmaf(vA, hA.z, acc.z); acc.w = fmaf(vA, hA.w, acc.w);
            acc.x = fmaf(vB, hB.x, acc.x); acc.y = fmaf(vB, hB.y, acc.y);
            acc.z = fmaf(vB, hB.z, acc.z); acc.w = fmaf(vB, hB.w, acc.w);
            acc.x = fmaf(vC, hC.x, acc.x); acc.y = fmaf(vC, hC.y, acc.y);
            acc.z = fmaf(vC, hC.z, acc.z); acc.w = fmaf(vC, hC.w, acc.w);
            acc.x = fmaf(vD, hD.x, acc.x); acc.y = fmaf(vD, hD.y, acc.y);
            acc.z = fmaf(vD, hD.z, acc.z); acc.w = fmaf(vD, hD.w, acc.w);
        }
        for (; j < n; j++) {
            int   s  = __shfl_sync(0xffffffffu, idx, j);
            float nv = __shfl_sync(0xffffffffu, v, j);
            float4 h = ld_h4(g_hWh + (size_t)s * FH + lane * 4);
            acc.x = fmaf(nv, h.x, acc.x);
            acc.y = fmaf(nv, h.y, acc.y);
            acc.z = fmaf(nv, h.z, acc.z);
            acc.w = fmaf(nv, h.w, acc.w);
        }
        e += n;
    }
    *(float4*)(g_c + (size_t)node * FH + lane * 4) = acc;
}

// ---------------- global mean pool (row-parallel, 512 threads) ------------
__device__ __forceinline__ int lbound(const int* a, int n, int key) {
    int lo = 0, hi = n;
    while (lo < hi) {
        int mid = (lo + hi) >> 1;
        if (a[mid] < key) lo = mid + 1; else hi = mid;
    }
    return lo;
}

__global__ void k_pool(const int* __restrict__ batch,
                       const float* __restrict__ b2, int M) {
    __shared__ float red[4][FH];
    int gi = blockIdx.x;
    int lo = lbound(batch, M, gi);
    int hi = lbound(batch, M, gi + 1);
    int t  = threadIdx.x;                 // 512
    int f  = t & 127;
    int rg = t >> 7;
    float s = 0.f;
    for (int i = lo + rg; i < hi; i += 4) s += g_c[(size_t)i * FH + f];
    red[rg][f] = s;
    __syncthreads();
    if (rg == 0) {
        float tot = red[0][f] + red[1][f] + red[2][f] + red[3][f];
        int cnt = hi - lo;
        g_pool[gi * FH + f] = (cnt > 0) ? tot / (float)cnt + b2[f] : 0.f;
    }
}

// ---------------- batched MLP head: C = act(A @ W + bias) ----------------
template <int K, bool RELU>
__global__ void k_mlp_g(const float* __restrict__ A, const float* __restrict__ W,
                        const float* __restrict__ bias, float* __restrict__ C,
                        int N) {
    __shared__ float As[16][131];
    __shared__ float Ws[128][64];
    int t = threadIdx.x;
    int col = t & 63, rg = t >> 6;
    int r0 = blockIdx.x * 16;
    int c0 = blockIdx.y * 64;
    float acc[4] = {0.f, 0.f, 0.f, 0.f};

    for (int kc = 0; kc < K; kc += 128) {
        for (int i = t; i < 16 * 128; i += 256) {
            int r = i >> 7, k = i & 127;
            As[r][k] = A[(size_t)(r0 + r) * K + kc + k];
        }
        for (int i = t; i < 128 * 64; i += 256) {
            int k = i >> 6, cc = i & 63;
            Ws[k][cc] = W[(size_t)(kc + k) * N + c0 + cc];
        }
        __syncthreads();
        #pragma unroll 4
        for (int k = 0; k < 128; k++) {
            float w = Ws[k][col];
            #pragma unroll
            for (int i2 = 0; i2 < 4; i2++)
                acc[i2] = fmaf(As[rg * 4 + i2][k], w, acc[i2]);
        }
        __syncthreads();
    }
    float b = bias[c0 + col];
    #pragma unroll
    for (int i2 = 0; i2 < 4; i2++) {
        float o = acc[i2] + b;
        if (RELU) o = fmaxf(o, 0.f);
        C[(size_t)(r0 + rg * 4 + i2) * N + c0 + col] = o;
    }
}

// ---------------- launch ----------------
extern "C" void kernel_launch(void* const* d_in, const int* in_sizes, int n_in,
                              void* d_out, int out_size) {
    const float* x     = (const float*)d_in[0];
    const int*   ei    = (const int*)d_in[1];
    const int*   batch = (const int*)d_in[2];
    const float* W0  = (const float*)d_in[3];
    const float* b0  = (const float*)d_in[4];
    const float* W1  = (const float*)d_in[5];
    const float* b1  = (const float*)d_in[6];
    const float* W2  = (const float*)d_in[7];
    const float* b2  = (const float*)d_in[8];
    const float* Wm1 = (const float*)d_in[9];
    const float* bm1 = (const float*)d_in[10];
    const float* Wm2 = (const float*)d_in[11];
    const float* bm2 = (const float*)d_in[12];
    float* out = (float*)d_out;

    const int M = in_sizes[0] / 64;
    const int E = in_sizes[1] / 2;

    const int smem64  = 2 * 128 * (64  + 8) * 2;
    const int smem128 = 2 * 128 * (128 + 8) * 2;
    static void *cnt_ptr = nullptr, *barc_ptr = nullptr, *barf_ptr = nullptr;
    static float *pool_ptr = nullptr, *m1_ptr = nullptr;
    static cudaStream_t s1 = nullptr;
    static cudaEvent_t evA = nullptr, evB = nullptr;
    if (!cnt_ptr) {
        cudaFuncSetAttribute(k_gemm_t<64,  false>, cudaFuncAttributeMaxDynamicSharedMemorySize, smem64);
        cudaFuncSetAttribute(k_gemm_t<128, true >, cudaFuncAttributeMaxDynamicSharedMemorySize, smem128);
        cudaGetSymbolAddress(&cnt_ptr,  g_cnt);
        cudaGetSymbolAddress(&barc_ptr, g_bar_cnt);
        cudaGetSymbolAddress(&barf_ptr, g_bar_flag);
        void* p;
        cudaGetSymbolAddress(&p, g_pool); pool_ptr = (float*)p;
        cudaGetSymbolAddress(&p, g_m1);   m1_ptr   = (float*)p;
        cudaStreamCreateWithFlags(&s1, cudaStreamNonBlocking);
        cudaEventCreateWithFlags(&evA, cudaEventDisableTiming);
        cudaEventCreateWithFlags(&evB, cudaEventDisableTiming);
    }

    const int TB = 256;
    int gbE2 = (E / 2 + TB - 1) / TB;      // 2 edges/thread (fill)
    int gbS  = (M + SCAN_B - 1) / SCAN_B;  // 196 blocks, all resident
    int gbG  = NPAD / 128;
    int gbC  = (M + 7) / 8;

    // fork: prep chain on s1, layer-0 GEMM on main stream (independent)
    cudaMemsetAsync(cnt_ptr,  0, (size_t)M * sizeof(int));
    cudaMemsetAsync(barc_ptr, 0, 2 * sizeof(int));
    cudaMemsetAsync(barf_ptr, 0, 2 * sizeof(int));
    cudaEventRecord(evA, 0);
    cudaStreamWaitEvent(s1, evA, 0);
    k_prep <<<gbS, SCAN_B, 0, s1>>>(ei, E, M);     // 0
    k_fill <<<gbE2, TB, 0, s1>>>(ei, E);           // 1
    cudaEventRecord(evB, s1);

    k_gemm_t<64, false><<<gbG, TB, smem64>>>(x, W0, nullptr, M);   // 2 ∥ prep
    cudaStreamWaitEvent(0, evB, 0);                                 // join

    k_conv  <<<gbC, TB>>>(M);                                       // 3 <- ncu
    k_gemm_t<128, true><<<gbG, TB, smem128>>>(nullptr, W1, b0, M);
    k_conv  <<<gbC, TB>>>(M);
    k_gemm_t<128, true><<<gbG, TB, smem128>>>(nullptr, W2, b1, M);
    k_conv  <<<gbC, TB>>>(M);

    k_pool<<<NOUT, 512>>>(batch, b2, M);
    dim3 gm1(NOUT / 16, NHID / 64);
    k_mlp_g<128, true ><<<gm1, TB>>>(pool_ptr, Wm1, bm1, m1_ptr, NHID);
    dim3 gm2(NOUT / 16, NOUT / 64);
    k_mlp_g<512, false><<<gm2, TB>>>(m1_ptr, Wm2, bm2, out, NOUT);
}

// round 16
// speedup vs baseline: 1.0642x; 1.0642x over previous
#include <cuda_runtime.h>
#include <cuda_fp16.h>
#include <cstdint>

// ---------------- problem constants ----------------
#define NMAX   50000
#define NPAD   50048
#define EMAX   800000
#define FH     128
#define NHID   512
#define NOUT   256
#define SCAN_B 256

// ---------------- device scratch (no allocs allowed) --------------
__device__ __half g_hWh[(size_t)NPAD * FH];
__device__ float  g_c  [(size_t)NPAD * FH];
__device__ float  g_dis[NMAX];
__device__ int    g_cnt [NMAX];
__device__ int    g_off [NMAX + 1];
__device__ int    g_fill[NMAX];
__device__ int    g_part[SCAN_B];
__device__ __align__(16) int2 g_edge[EMAX];  // packed (src, norm); 16B-aligned
__device__ float  g_pool[NOUT * FH];
__device__ float  g_m1  [NOUT * NHID];

// ---------------- graph-prep kernels (R14 measured-good config) -----------
__global__ void k_count(const int* __restrict__ ei, int E) {
    int e = blockIdx.x * blockDim.x + threadIdx.x;
    if (e < E) atomicAdd(&g_cnt[ei[E + e]], 1);
}

__global__ void k_scan1(int M) {
    __shared__ int red[SCAN_B];
    int t = threadIdx.x;
    int i = blockIdx.x * SCAN_B + t;
    int v = (i < M) ? g_cnt[i] : 0;
    if (i < M) g_dis[i] = rsqrtf((float)(v + 1));      // +1 self loop
    red[t] = v;
    __syncthreads();
    for (int d = SCAN_B / 2; d > 0; d >>= 1) {
        if (t < d) red[t] += red[t + d];
        __syncthreads();
    }
    if (t == 0) g_part[blockIdx.x] = red[0];
}

__global__ void k_scan23(int M, int nb) {
    __shared__ int sm[SCAN_B];
    int t = threadIdx.x, bid = blockIdx.x;
    int pv = (t < nb) ? g_part[t] : 0;
    sm[t] = pv;
    __syncthreads();
    for (int d = 1; d < SCAN_B; d <<= 1) {
        int add = (t >= d) ? sm[t - d] : 0;
        __syncthreads();
        sm[t] += add;
        __syncthreads();
    }
    int base  = sm[bid] - g_part[bid];
    int total = sm[SCAN_B - 1];
    __syncthreads();
    int i = bid * SCAN_B + t;
    int v = (i < M) ? g_cnt[i] : 0;
    sm[t] = v;
    __syncthreads();
    for (int d = 1; d < SCAN_B; d <<= 1) {
        int add = (t >= d) ? sm[t - d] : 0;
        __syncthreads();
        sm[t] += add;
        __syncthreads();
    }
    if (i < M) {
        int ex = base + sm[t] - v;
        g_off[i]  = ex;
        g_fill[i] = ex;
    }
    if (bid == 0 && t == 0) g_off[M] = total;
}

// 2 edges/thread (1563 blocks)
__global__ void k_fill(const int* __restrict__ ei, int E) {
    int base = (blockIdx.x * blockDim.x + threadIdx.x) * 2;
    if (base + 1 < E) {
        int2 s2 = *(const int2*)(ei + base);
        int2 d2 = *(const int2*)(ei + E + base);
        float ds0 = g_dis[s2.x], dd0 = g_dis[d2.x];
        float ds1 = g_dis[s2.y], dd1 = g_dis[d2.y];
        int p0 = atomicAdd(&g_fill[d2.x], 1);
        int p1 = atomicAdd(&g_fill[d2.y], 1);
        g_edge[p0] = make_int2(s2.x, __float_as_int(ds0 * dd0));
        g_edge[p1] = make_int2(s2.y, __float_as_int(ds1 * dd1));
    } else if (base < E) {
        int s = ei[base];
        int d = ei[E + base];
        int p = atomicAdd(&g_fill[d], 1);
        g_edge[p] = make_int2(s, __float_as_int(g_dis[s] * g_dis[d]));
    }
}

// ---------------- tensor-core node GEMM: g_hWh = half(act(A) @ W) ---------
template <int K, bool FROM_C>
__global__ void __launch_bounds__(256, 2)
k_gemm_t(const float* __restrict__ X, const float* __restrict__ W,
         const float* __restrict__ bias, int M) {
    extern __shared__ __half sh[];
    const int LDA = K + 8;
    __half* As = sh;                    // [128][LDA]
    __half* Bs = sh + 128 * LDA;        // [128][LDA]  (Bs[n][k] = W[k][n])
    int t  = threadIdx.x;
    int m0 = blockIdx.x * 128;
    const float* A = FROM_C ? g_c : X;

    {
        const float4* W4 = (const float4*)W;
        for (int i = t; i < K * 32; i += 256) {
            int k  = i >> 5;
            int n4 = (i & 31) << 2;
            float4 w = W4[i];
            Bs[(n4 + 0) * LDA + k] = __float2half(w.x);
            Bs[(n4 + 1) * LDA + k] = __float2half(w.y);
            Bs[(n4 + 2) * LDA + k] = __float2half(w.z);
            Bs[(n4 + 3) * LDA + k] = __float2half(w.w);
        }
    }
    {
        const int rw = K / 8;
        for (int i = t; i < 128 * rw; i += 256) {
            int r  = i / rw;
            int c8 = (i - r * rw) * 8;
            int row = m0 + r;
            float4 v0 = make_float4(0.f, 0.f, 0.f, 0.f), v1 = v0;
            if (row < M) {
                v0 = *(const float4*)(A + (size_t)row * K + c8);
                v1 = *(const float4*)(A + (size_t)row * K + c8 + 4);
            }
            if (FROM_C) {
                float4 ba = ((const float4*)bias)[c8 >> 2];
                float4 bb = ((const float4*)bias)[(c8 >> 2) + 1];
                v0.x = fmaxf(v0.x + ba.x, 0.f); v0.y = fmaxf(v0.y + ba.y, 0.f);
                v0.z = fmaxf(v0.z + ba.z, 0.f); v0.w = fmaxf(v0.w + ba.w, 0.f);
                v1.x = fmaxf(v1.x + bb.x, 0.f); v1.y = fmaxf(v1.y + bb.y, 0.f);
                v1.z = fmaxf(v1.z + bb.z, 0.f); v1.w = fmaxf(v1.w + bb.w, 0.f);
            }
            __half2 h0 = __floats2half2_rn(v0.x, v0.y);
            __half2 h1 = __floats2half2_rn(v0.z, v0.w);
            __half2 h2 = __floats2half2_rn(v1.x, v1.y);
            __half2 h3 = __floats2half2_rn(v1.z, v1.w);
            uint4 pk = make_uint4(*(unsigned*)&h0, *(unsigned*)&h1,
                                  *(unsigned*)&h2, *(unsigned*)&h3);
            *(uint4*)(As + r * LDA + c8) = pk;
        }
    }
    __syncthreads();

    int lane = t & 31;
    int wid  = t >> 5;
    int wm = wid & 3;
    int wn = wid >> 2;
    int g  = lane >> 2;
    int tg = lane & 3;

    float c[2][8][4];
    #pragma unroll
    for (int mi = 0; mi < 2; mi++)
        #pragma unroll
        for (int ni = 0; ni < 8; ni++)
            #pragma unroll
            for (int q = 0; q < 4; q++) c[mi][ni][q] = 0.f;

    #pragma unroll
    for (int k0 = 0; k0 < K; k0 += 16) {
        uint32_t a[2][4], b[8][2];
        #pragma unroll
        for (int mi = 0; mi < 2; mi++) {
            int r = wm * 32 + mi * 16 + g;
            const __half* p = As + r * LDA + k0 + tg * 2;
            a[mi][0] = *(const uint32_t*)p;
            a[mi][1] = *(const uint32_t*)(p + 8 * LDA);
            a[mi][2] = *(const uint32_t*)(p + 8);
            a[mi][3] = *(const uint32_t*)(p + 8 * LDA + 8);
        }
        #pragma unroll
        for (int ni = 0; ni < 8; ni++) {
            int n = wn * 64 + ni * 8 + g;
            const __half* p = Bs + n * LDA + k0 + tg * 2;
            b[ni][0] = *(const uint32_t*)p;
            b[ni][1] = *(const uint32_t*)(p + 8);
        }
        #pragma unroll
        for (int mi = 0; mi < 2; mi++)
            #pragma unroll
            for (int ni = 0; ni < 8; ni++)
                asm volatile(
                    "mma.sync.aligned.m16n8k16.row.col.f32.f16.f16.f32 "
                    "{%0,%1,%2,%3}, {%4,%5,%6,%7}, {%8,%9}, {%0,%1,%2,%3};"
                    : "+f"(c[mi][ni][0]), "+f"(c[mi][ni][1]),
                      "+f"(c[mi][ni][2]), "+f"(c[mi][ni][3])
                    : "r"(a[mi][0]), "r"(a[mi][1]), "r"(a[mi][2]), "r"(a[mi][3]),
                      "r"(b[ni][0]), "r"(b[ni][1]));
    }

    #pragma unroll
    for (int mi = 0; mi < 2; mi++) {
        int r0 = m0 + wm * 32 + mi * 16 + g;
        #pragma unroll
        for (int ni = 0; ni < 8; ni++) {
            int col = wn * 64 + ni * 8 + tg * 2;
            __half2 lo = __floats2half2_rn(c[mi][ni][0], c[mi][ni][1]);
            __half2 hi = __floats2half2_rn(c[mi][ni][2], c[mi][ni][3]);
            *(__half2*)(g_hWh + (size_t)r0 * FH + col)        = lo;
            *(__half2*)(g_hWh + (size_t)(r0 + 8) * FH + col)  = hi;
        }
    }
}

// ---------------- conv: g_c[dst] = sum_e norm_e * half(g_hWh[src]) --------
// edge (src,norm) read via UNIFORM LDG (warp broadcast, L1-resident) —
// no shfl staging, no chunk bookkeeping. FMA order identical to before.
__device__ __forceinline__ float4 ld_h4(const __half* p) {
    uint2 u = *(const uint2*)p;
    __half2 a = *(__half2*)&u.x;
    __half2 b = *(__half2*)&u.y;
    float2 fa = __half22float2(a);
    float2 fb = __half22float2(b);
    return make_float4(fa.x, fa.y, fb.x, fb.y);
}

__global__ void __launch_bounds__(256, 7) k_conv(int M) {
    int warp = (blockIdx.x * blockDim.x + threadIdx.x) >> 5;
    if (warp >= M) return;
    int lane = threadIdx.x & 31;
    int node = warp;

    float d  = g_dis[node];
    float s0 = d * d;
    float4 h0 = ld_h4(g_hWh + (size_t)node * FH + lane * 4);
    float4 acc = make_float4(s0 * h0.x, s0 * h0.y, s0 * h0.z, s0 * h0.w);

    int e  = g_off[node];
    int e1 = g_off[node + 1];
    // peel to even index so int4 (2-edge) loads are 16B-aligned
    if (e < e1 && (e & 1)) {
        int2 p = g_edge[e];
        float nv = __int_as_float(p.y);
        float4 h = ld_h4(g_hWh + (size_t)p.x * FH + lane * 4);
        acc.x = fmaf(nv, h.x, acc.x); acc.y = fmaf(nv, h.y, acc.y);
        acc.z = fmaf(nv, h.z, acc.z); acc.w = fmaf(nv, h.w, acc.w);
        e++;
    }
    for (; e + 4 <= e1; e += 4) {
        int4 pA = *(const int4*)&g_edge[e];        // edges e, e+1
        int4 pB = *(const int4*)&g_edge[e + 2];    // edges e+2, e+3
        float4 hA = ld_h4(g_hWh + (size_t)pA.x * FH + lane * 4);
        float4 hB = ld_h4(g_hWh + (size_t)pA.z * FH + lane * 4);
        float4 hC = ld_h4(g_hWh + (size_t)pB.x * FH + lane * 4);
        float4 hD = ld_h4(g_hWh + (size_t)pB.z * FH + lane * 4);
        float vA = __int_as_float(pA.y);
        float vB = __int_as_float(pA.w);
        float vC = __int_as_float(pB.y);
        float vD = __int_as_float(pB.w);
        acc.x = fmaf(vA, hA.x, acc.x); acc.y = fmaf(vA, hA.y, acc.y);
        acc.z = fmaf(vA, hA.z, acc.z); acc.w = fmaf(vA, hA.w, acc.w);
        acc.x = fmaf(vB, hB.x, acc.x); acc.y = fmaf(vB, hB.y, acc.y);
        acc.z = fmaf(vB, hB.z, acc.z); acc.w = fmaf(vB, hB.w, acc.w);
        acc.x = fmaf(vC, hC.x, acc.x); acc.y = fmaf(vC, hC.y, acc.y);
        acc.z = fmaf(vC, hC.z, acc.z); acc.w = fmaf(vC, hC.w, acc.w);
        acc.x = fmaf(vD, hD.x, acc.x); acc.y = fmaf(vD, hD.y, acc.y);
        acc.z = fmaf(vD, hD.z, acc.z); acc.w = fmaf(vD, hD.w, acc.w);
    }
    for (; e < e1; e++) {
        int2 p = g_edge[e];
        float nv = __int_as_float(p.y);
        float4 h = ld_h4(g_hWh + (size_t)p.x * FH + lane * 4);
        acc.x = fmaf(nv, h.x, acc.x); acc.y = fmaf(nv, h.y, acc.y);
        acc.z = fmaf(nv, h.z, acc.z); acc.w = fmaf(nv, h.w, acc.w);
    }
    *(float4*)(g_c + (size_t)node * FH + lane * 4) = acc;
}

// ---------------- global mean pool (row-parallel, 512 threads) ------------
__device__ __forceinline__ int lbound(const int* a, int n, int key) {
    int lo = 0, hi = n;
    while (lo < hi) {
        int mid = (lo + hi) >> 1;
        if (a[mid] < key) lo = mid + 1; else hi = mid;
    }
    return lo;
}

__global__ void k_pool(const int* __restrict__ batch,
                       const float* __restrict__ b2, int M) {
    __shared__ float red[4][FH];
    int gi = blockIdx.x;
    int lo = lbound(batch, M, gi);
    int hi = lbound(batch, M, gi + 1);
    int t  = threadIdx.x;                 // 512
    int f  = t & 127;
    int rg = t >> 7;
    float s = 0.f;
    for (int i = lo + rg; i < hi; i += 4) s += g_c[(size_t)i * FH + f];
    red[rg][f] = s;
    __syncthreads();
    if (rg == 0) {
        float tot = red[0][f] + red[1][f] + red[2][f] + red[3][f];
        int cnt = hi - lo;
        g_pool[gi * FH + f] = (cnt > 0) ? tot / (float)cnt + b2[f] : 0.f;
    }
}

// ---------------- batched MLP head: C = act(A @ W + bias) ----------------
template <int K, bool RELU>
__global__ void k_mlp_g(const float* __restrict__ A, const float* __restrict__ W,
                        const float* __restrict__ bias, float* __restrict__ C,
                        int N) {
    __shared__ float As[16][131];
    __shared__ float Ws[128][64];
    int t = threadIdx.x;
    int col = t & 63, rg = t >> 6;
    int r0 = blockIdx.x * 16;
    int c0 = blockIdx.y * 64;
    float acc[4] = {0.f, 0.f, 0.f, 0.f};

    for (int kc = 0; kc < K; kc += 128) {
        for (int i = t; i < 16 * 128; i += 256) {
            int r = i >> 7, k = i & 127;
            As[r][k] = A[(size_t)(r0 + r) * K + kc + k];
        }
        for (int i = t; i < 128 * 64; i += 256) {
            int k = i >> 6, cc = i & 63;
            Ws[k][cc] = W[(size_t)(kc + k) * N + c0 + cc];
        }
        __syncthreads();
        #pragma unroll 4
        for (int k = 0; k < 128; k++) {
            float w = Ws[k][col];
            #pragma unroll
            for (int i2 = 0; i2 < 4; i2++)
                acc[i2] = fmaf(As[rg * 4 + i2][k], w, acc[i2]);
        }
        __syncthreads();
    }
    float b = bias[c0 + col];
    #pragma unroll
    for (int i2 = 0; i2 < 4; i2++) {
        float o = acc[i2] + b;
        if (RELU) o = fmaxf(o, 0.f);
        C[(size_t)(r0 + rg * 4 + i2) * N + c0 + col] = o;
    }
}

// ---------------- launch ----------------
extern "C" void kernel_launch(void* const* d_in, const int* in_sizes, int n_in,
                              void* d_out, int out_size) {
    const float* x     = (const float*)d_in[0];
    const int*   ei    = (const int*)d_in[1];
    const int*   batch = (const int*)d_in[2];
    const float* W0  = (const float*)d_in[3];
    const float* b0  = (const float*)d_in[4];
    const float* W1  = (const float*)d_in[5];
    const float* b1  = (const float*)d_in[6];
    const float* W2  = (const float*)d_in[7];
    const float* b2  = (const float*)d_in[8];
    const float* Wm1 = (const float*)d_in[9];
    const float* bm1 = (const float*)d_in[10];
    const float* Wm2 = (const float*)d_in[11];
    const float* bm2 = (const float*)d_in[12];
    float* out = (float*)d_out;

    const int M = in_sizes[0] / 64;
    const int E = in_sizes[1] / 2;

    const int smem64  = 2 * 128 * (64  + 8) * 2;
    const int smem128 = 2 * 128 * (128 + 8) * 2;
    static void* cnt_ptr = nullptr;
    static float *pool_ptr = nullptr, *m1_ptr = nullptr;
    static cudaStream_t s1 = nullptr;
    static cudaEvent_t evA = nullptr, evB = nullptr;
    if (!cnt_ptr) {
        cudaFuncSetAttribute(k_gemm_t<64,  false>, cudaFuncAttributeMaxDynamicSharedMemorySize, smem64);
        cudaFuncSetAttribute(k_gemm_t<128, true >, cudaFuncAttributeMaxDynamicSharedMemorySize, smem128);
        cudaGetSymbolAddress(&cnt_ptr, g_cnt);
        void* p;
        cudaGetSymbolAddress(&p, g_pool); pool_ptr = (float*)p;
        cudaGetSymbolAddress(&p, g_m1);   m1_ptr   = (float*)p;
        cudaStreamCreateWithFlags(&s1, cudaStreamNonBlocking);
        cudaEventCreateWithFlags(&evA, cudaEventDisableTiming);
        cudaEventCreateWithFlags(&evB, cudaEventDisableTiming);
    }

    const int TB = 256;
    int gbE1 = (E + TB - 1) / TB;          // 1 edge/thread (count)
    int gbE2 = (E / 2 + TB - 1) / TB;      // 2 edges/thread (fill)
    int gbS  = (M + SCAN_B - 1) / SCAN_B;
    int gbG  = NPAD / 128;
    int gbC  = (M + 7) / 8;

    // fork: prep chain on s1, layer-0 GEMM on main stream (independent)
    cudaMemsetAsync(cnt_ptr, 0, (size_t)M * sizeof(int));
    cudaEventRecord(evA, 0);
    cudaStreamWaitEvent(s1, evA, 0);
    k_count <<<gbE1, TB, 0, s1>>>(ei, E);          // 0
    k_scan1 <<<gbS, SCAN_B, 0, s1>>>(M);           // 1
    k_scan23<<<gbS, SCAN_B, 0, s1>>>(M, gbS);      // 2
    k_fill  <<<gbE2, TB, 0, s1>>>(ei, E);          // 3 <- ncu (regression guard)
    cudaEventRecord(evB, s1);

    k_gemm_t<64, false><<<gbG, TB, smem64>>>(x, W0, nullptr, M);   // ∥ prep
    cudaStreamWaitEvent(0, evB, 0);                                 // join

    k_conv  <<<gbC, TB>>>(M);
    k_gemm_t<128, true><<<gbG, TB, smem128>>>(nullptr, W1, b0, M);
    k_conv  <<<gbC, TB>>>(M);
    k_gemm_t<128, true><<<gbG, TB, smem128>>>(nullptr, W2, b1, M);
    k_conv  <<<gbC, TB>>>(M);

    k_pool<<<NOUT, 512>>>(batch, b2, M);
    dim3 gm1(NOUT / 16, NHID / 64);
    k_mlp_g<128, true ><<<gm1, TB>>>(pool_ptr, Wm1, bm1, m1_ptr, NHID);
    dim3 gm2(NOUT / 16, NOUT / 64);
    k_mlp_g<512, false><<<gm2, TB>>>(m1_ptr, Wm2, bm2, out, NOUT);
}

// round 17
// speedup vs baseline: 1.0774x; 1.0124x over previous
#include <cuda_runtime.h>
#include <cuda_fp16.h>
#include <cstdint>

// ---------------- problem constants ----------------
#define NMAX   50000
#define NPAD   50048
#define EMAX   800000
#define FH     128
#define NHID   512
#define NOUT   256
#define SCAN_B 256

// ---------------- device scratch (no allocs allowed) --------------
__device__ __half g_hWh[(size_t)NPAD * FH];  // GEMM output fp16
__device__ __half g_ch [(size_t)NPAD * FH];  // conv output fp16
__device__ float  g_dis[NMAX];
__device__ int    g_cnt [NMAX];              // self-cleaning (scan23 zeroes)
__device__ int    g_off [NMAX + 1];
__device__ int    g_fill[NMAX];
__device__ int    g_part[SCAN_B];
__device__ __align__(16) int2 g_edge[EMAX];  // packed (src, norm)
__device__ float  g_pool[NOUT * FH];
__device__ float  g_m1  [NOUT * NHID];

// ---------------- graph-prep kernels (R14 measured-good config) -----------
__global__ void k_count(const int* __restrict__ ei, int E) {
    int e = blockIdx.x * blockDim.x + threadIdx.x;
    if (e < E) atomicAdd(&g_cnt[ei[E + e]], 1);
}

__global__ void k_scan1(int M) {
    __shared__ int red[SCAN_B];
    int t = threadIdx.x;
    int i = blockIdx.x * SCAN_B + t;
    int v = (i < M) ? g_cnt[i] : 0;
    if (i < M) g_dis[i] = rsqrtf((float)(v + 1));      // +1 self loop
    red[t] = v;
    __syncthreads();
    for (int d = SCAN_B / 2; d > 0; d >>= 1) {
        if (t < d) red[t] += red[t + d];
        __syncthreads();
    }
    if (t == 0) g_part[blockIdx.x] = red[0];
}

__global__ void k_scan23(int M, int nb) {
    __shared__ int sm[SCAN_B];
    int t = threadIdx.x, bid = blockIdx.x;
    int pv = (t < nb) ? g_part[t] : 0;
    sm[t] = pv;
    __syncthreads();
    for (int d = 1; d < SCAN_B; d <<= 1) {
        int add = (t >= d) ? sm[t - d] : 0;
        __syncthreads();
        sm[t] += add;
        __syncthreads();
    }
    int base  = sm[bid] - g_part[bid];
    int total = sm[SCAN_B - 1];
    __syncthreads();
    int i = bid * SCAN_B + t;
    int v = (i < M) ? g_cnt[i] : 0;
    sm[t] = v;
    __syncthreads();
    for (int d = 1; d < SCAN_B; d <<= 1) {
        int add = (t >= d) ? sm[t - d] : 0;
        __syncthreads();
        sm[t] += add;
        __syncthreads();
    }
    if (i < M) {
        int ex = base + sm[t] - v;
        g_off[i]  = ex;
        g_fill[i] = ex;
        g_cnt[i]  = 0;                 // self-clean for next graph replay
    }
    if (bid == 0 && t == 0) g_off[M] = total;
}

// 2 edges/thread (1563 blocks)
__global__ void k_fill(const int* __restrict__ ei, int E) {
    int base = (blockIdx.x * blockDim.x + threadIdx.x) * 2;
    if (base + 1 < E) {
        int2 s2 = *(const int2*)(ei + base);
        int2 d2 = *(const int2*)(ei + E + base);
        float ds0 = g_dis[s2.x], dd0 = g_dis[d2.x];
        float ds1 = g_dis[s2.y], dd1 = g_dis[d2.y];
        int p0 = atomicAdd(&g_fill[d2.x], 1);
        int p1 = atomicAdd(&g_fill[d2.y], 1);
        g_edge[p0] = make_int2(s2.x, __float_as_int(ds0 * dd0));
        g_edge[p1] = make_int2(s2.y, __float_as_int(ds1 * dd1));
    } else if (base < E) {
        int s = ei[base];
        int d = ei[E + base];
        int p = atomicAdd(&g_fill[d], 1);
        g_edge[p] = make_int2(s, __float_as_int(g_dis[s] * g_dis[d]));
    }
}

// ---------------- tensor-core node GEMM: g_hWh = half(act(A) @ W) ---------
// FROM_C: A = g_ch (fp16) with fused fp16 bias+ReLU. else A = X (fp32).
template <int K, bool FROM_C>
__global__ void __launch_bounds__(256, 2)
k_gemm_t(const float* __restrict__ X, const float* __restrict__ W,
         const float* __restrict__ bias, int M) {
    extern __shared__ __half sh[];
    const int LDA = K + 8;
    __half*  As = sh;                       // [128][LDA]
    __half*  Bs = sh + 128 * LDA;           // [128][LDA]  (Bs[n][k] = W[k][n])
    __half2* bsh = (__half2*)(sh + 2 * 128 * LDA);   // [64] fp16 bias
    int t  = threadIdx.x;
    int m0 = blockIdx.x * 128;

    if (FROM_C && t < 64) {
        float2 bf = ((const float2*)bias)[t];
        bsh[t] = __floats2half2_rn(bf.x, bf.y);
    }
    {   // stage W transposed
        const float4* W4 = (const float4*)W;
        for (int i = t; i < K * 32; i += 256) {
            int k  = i >> 5;
            int n4 = (i & 31) << 2;
            float4 w = W4[i];
            Bs[(n4 + 0) * LDA + k] = __float2half(w.x);
            Bs[(n4 + 1) * LDA + k] = __float2half(w.y);
            Bs[(n4 + 2) * LDA + k] = __float2half(w.z);
            Bs[(n4 + 3) * LDA + k] = __float2half(w.w);
        }
    }
    __syncthreads();   // bsh ready before A staging uses it

    if (FROM_C) {      // half source: uint4 = 8 halfs, fp16 bias+ReLU
        for (int i = t; i < 128 * (K / 8); i += 256) {
            int r  = i >> 4;
            int c8 = (i & 15) * 8;
            int row = m0 + r;
            uint4 v = make_uint4(0, 0, 0, 0);
            if (row < M) v = *(const uint4*)(g_ch + (size_t)row * FH + c8);
            __half2* hv = (__half2*)&v;
            __half2 z = __floats2half2_rn(0.f, 0.f);
            #pragma unroll
            for (int q = 0; q < 4; q++)
                hv[q] = __hmax2(__hadd2(hv[q], bsh[(c8 >> 1) + q]), z);
            *(uint4*)(As + r * LDA + c8) = v;
        }
    } else {           // fp32 source (layer 0)
        const int rw = K / 8;
        for (int i = t; i < 128 * rw; i += 256) {
            int r  = i / rw;
            int c8 = (i - r * rw) * 8;
            int row = m0 + r;
            float4 v0 = make_float4(0.f, 0.f, 0.f, 0.f), v1 = v0;
            if (row < M) {
                v0 = *(const float4*)(X + (size_t)row * K + c8);
                v1 = *(const float4*)(X + (size_t)row * K + c8 + 4);
            }
            __half2 h0 = __floats2half2_rn(v0.x, v0.y);
            __half2 h1 = __floats2half2_rn(v0.z, v0.w);
            __half2 h2 = __floats2half2_rn(v1.x, v1.y);
            __half2 h3 = __floats2half2_rn(v1.z, v1.w);
            uint4 pk = make_uint4(*(unsigned*)&h0, *(unsigned*)&h1,
                                  *(unsigned*)&h2, *(unsigned*)&h3);
            *(uint4*)(As + r * LDA + c8) = pk;
        }
    }
    __syncthreads();

    int lane = t & 31;
    int wid  = t >> 5;
    int wm = wid & 3;
    int wn = wid >> 2;
    int g  = lane >> 2;
    int tg = lane & 3;

    float c[2][8][4];
    #pragma unroll
    for (int mi = 0; mi < 2; mi++)
        #pragma unroll
        for (int ni = 0; ni < 8; ni++)
            #pragma unroll
            for (int q = 0; q < 4; q++) c[mi][ni][q] = 0.f;

    #pragma unroll
    for (int k0 = 0; k0 < K; k0 += 16) {
        uint32_t a[2][4], b[8][2];
        #pragma unroll
        for (int mi = 0; mi < 2; mi++) {
            int r = wm * 32 + mi * 16 + g;
            const __half* p = As + r * LDA + k0 + tg * 2;
            a[mi][0] = *(const uint32_t*)p;
            a[mi][1] = *(const uint32_t*)(p + 8 * LDA);
            a[mi][2] = *(const uint32_t*)(p + 8);
            a[mi][3] = *(const uint32_t*)(p + 8 * LDA + 8);
        }
        #pragma unroll
        for (int ni = 0; ni < 8; ni++) {
            int n = wn * 64 + ni * 8 + g;
            const __half* p = Bs + n * LDA + k0 + tg * 2;
            b[ni][0] = *(const uint32_t*)p;
            b[ni][1] = *(const uint32_t*)(p + 8);
        }
        #pragma unroll
        for (int mi = 0; mi < 2; mi++)
            #pragma unroll
            for (int ni = 0; ni < 8; ni++)
                asm volatile(
                    "mma.sync.aligned.m16n8k16.row.col.f32.f16.f16.f32 "
                    "{%0,%1,%2,%3}, {%4,%5,%6,%7}, {%8,%9}, {%0,%1,%2,%3};"
                    : "+f"(c[mi][ni][0]), "+f"(c[mi][ni][1]),
                      "+f"(c[mi][ni][2]), "+f"(c[mi][ni][3])
                    : "r"(a[mi][0]), "r"(a[mi][1]), "r"(a[mi][2]), "r"(a[mi][3]),
                      "r"(b[ni][0]), "r"(b[ni][1]));
    }

    #pragma unroll
    for (int mi = 0; mi < 2; mi++) {
        int r0 = m0 + wm * 32 + mi * 16 + g;
        #pragma unroll
        for (int ni = 0; ni < 8; ni++) {
            int col = wn * 64 + ni * 8 + tg * 2;
            __half2 lo = __floats2half2_rn(c[mi][ni][0], c[mi][ni][1]);
            __half2 hi = __floats2half2_rn(c[mi][ni][2], c[mi][ni][3]);
            *(__half2*)(g_hWh + (size_t)r0 * FH + col)        = lo;
            *(__half2*)(g_hWh + (size_t)(r0 + 8) * FH + col)  = hi;
        }
    }
}

// ---------------- conv: g_ch[dst] = half(sum_e norm_e * g_hWh[src]) -------
// R14 shfl variant (measured best), fp16 output store.
__device__ __forceinline__ float4 ld_h4(const __half* p) {
    uint2 u = *(const uint2*)p;
    __half2 a = *(__half2*)&u.x;
    __half2 b = *(__half2*)&u.y;
    float2 fa = __half22float2(a);
    float2 fb = __half22float2(b);
    return make_float4(fa.x, fa.y, fb.x, fb.y);
}

__global__ void __launch_bounds__(256, 7) k_conv(int M) {
    int warp = (blockIdx.x * blockDim.x + threadIdx.x) >> 5;
    if (warp >= M) return;
    int lane = threadIdx.x & 31;
    int node = warp;

    float d  = g_dis[node];
    float s0 = d * d;
    float4 h0 = ld_h4(g_hWh + (size_t)node * FH + lane * 4);
    float4 acc = make_float4(s0 * h0.x, s0 * h0.y, s0 * h0.z, s0 * h0.w);

    int e  = g_off[node];
    int e1 = g_off[node + 1];
    while (e < e1) {
        int n = e1 - e; if (n > 32) n = 32;
        int   idx = 0;
        float v   = 0.f;
        if (lane < n) {
            int2 pk = g_edge[e + lane];
            idx = pk.x; v = __int_as_float(pk.y);
        }
        int j = 0;
        for (; j + 4 <= n; j += 4) {
            int   sA = __shfl_sync(0xffffffffu, idx, j);
            int   sB = __shfl_sync(0xffffffffu, idx, j + 1);
            int   sC = __shfl_sync(0xffffffffu, idx, j + 2);
            int   sD = __shfl_sync(0xffffffffu, idx, j + 3);
            float vA = __shfl_sync(0xffffffffu, v, j);
            float vB = __shfl_sync(0xffffffffu, v, j + 1);
            float vC = __shfl_sync(0xffffffffu, v, j + 2);
            float vD = __shfl_sync(0xffffffffu, v, j + 3);
            float4 hA = ld_h4(g_hWh + (size_t)sA * FH + lane * 4);
            float4 hB = ld_h4(g_hWh + (size_t)sB * FH + lane * 4);
            float4 hC = ld_h4(g_hWh + (size_t)sC * FH + lane * 4);
            float4 hD = ld_h4(g_hWh + (size_t)sD * FH + lane * 4);
            acc.x = fmaf(vA, hA.x, acc.x); acc.y = fmaf(vA, hA.y, acc.y);
            acc.z = fmaf(vA, hA.z, acc.z); acc.w = fmaf(vA, hA.w, acc.w);
            acc.x = fmaf(vB, hB.x, acc.x); acc.y = fmaf(vB, hB.y, acc.y);
            acc.z = fmaf(vB, hB.z, acc.z); acc.w = fmaf(vB, hB.w, acc.w);
            acc.x = fmaf(vC, hC.x, acc.x); acc.y = fmaf(vC, hC.y, acc.y);
            acc.z = fmaf(vC, hC.z, acc.z); acc.w = fmaf(vC, hC.w, acc.w);
            acc.x = fmaf(vD, hD.x, acc.x); acc.y = fmaf(vD, hD.y, acc.y);
            acc.z = fmaf(vD, hD.z, acc.z); acc.w = fmaf(vD, hD.w, acc.w);
        }
        for (; j < n; j++) {
            int   s  = __shfl_sync(0xffffffffu, idx, j);
            float nv = __shfl_sync(0xffffffffu, v, j);
            float4 h = ld_h4(g_hWh + (size_t)s * FH + lane * 4);
            acc.x = fmaf(nv, h.x, acc.x);
            acc.y = fmaf(nv, h.y, acc.y);
            acc.z = fmaf(nv, h.z, acc.z);
            acc.w = fmaf(nv, h.w, acc.w);
        }
        e += n;
    }
    __half2 o0 = __floats2half2_rn(acc.x, acc.y);
    __half2 o1 = __floats2half2_rn(acc.z, acc.w);
    *(uint2*)(g_ch + (size_t)node * FH + lane * 4) =
        make_uint2(*(unsigned*)&o0, *(unsigned*)&o1);
}

// ---------------- global mean pool (row-parallel, 512 threads) ------------
__device__ __forceinline__ int lbound(const int* a, int n, int key) {
    int lo = 0, hi = n;
    while (lo < hi) {
        int mid = (lo + hi) >> 1;
        if (a[mid] < key) lo = mid + 1; else hi = mid;
    }
    return lo;
}

__global__ void k_pool(const int* __restrict__ batch,
                       const float* __restrict__ b2, int M) {
    __shared__ float red[4][FH];
    int gi = blockIdx.x;
    int lo = lbound(batch, M, gi);
    int hi = lbound(batch, M, gi + 1);
    int t  = threadIdx.x;                 // 512
    int f  = t & 127;
    int rg = t >> 7;
    float s = 0.f;
    for (int i = lo + rg; i < hi; i += 4)
        s += __half2float(g_ch[(size_t)i * FH + f]);
    red[rg][f] = s;
    __syncthreads();
    if (rg == 0) {
        float tot = red[0][f] + red[1][f] + red[2][f] + red[3][f];
        int cnt = hi - lo;
        g_pool[gi * FH + f] = (cnt > 0) ? tot / (float)cnt + b2[f] : 0.f;
    }
}

// ---------------- batched MLP head: C = act(A @ W + bias) ----------------
template <int K, bool RELU>
__global__ void k_mlp_g(const float* __restrict__ A, const float* __restrict__ W,
                        const float* __restrict__ bias, float* __restrict__ C,
                        int N) {
    __shared__ float As[16][131];
    __shared__ float Ws[128][64];
    int t = threadIdx.x;
    int col = t & 63, rg = t >> 6;
    int r0 = blockIdx.x * 16;
    int c0 = blockIdx.y * 64;
    float acc[4] = {0.f, 0.f, 0.f, 0.f};

    for (int kc = 0; kc < K; kc += 128) {
        for (int i = t; i < 16 * 128; i += 256) {
            int r = i >> 7, k = i & 127;
            As[r][k] = A[(size_t)(r0 + r) * K + kc + k];
        }
        for (int i = t; i < 128 * 64; i += 256) {
            int k = i >> 6, cc = i & 63;
            Ws[k][cc] = W[(size_t)(kc + k) * N + c0 + cc];
        }
        __syncthreads();
        #pragma unroll 4
        for (int k = 0; k < 128; k++) {
            float w = Ws[k][col];
            #pragma unroll
            for (int i2 = 0; i2 < 4; i2++)
                acc[i2] = fmaf(As[rg * 4 + i2][k], w, acc[i2]);
        }
        __syncthreads();
    }
    float b = bias[c0 + col];
    #pragma unroll
    for (int i2 = 0; i2 < 4; i2++) {
        float o = acc[i2] + b;
        if (RELU) o = fmaxf(o, 0.f);
        C[(size_t)(r0 + rg * 4 + i2) * N + c0 + col] = o;
    }
}

// ---------------- launch ----------------
extern "C" void kernel_launch(void* const* d_in, const int* in_sizes, int n_in,
                              void* d_out, int out_size) {
    const float* x     = (const float*)d_in[0];
    const int*   ei    = (const int*)d_in[1];
    const int*   batch = (const int*)d_in[2];
    const float* W0  = (const float*)d_in[3];
    const float* b0  = (const float*)d_in[4];
    const float* W1  = (const float*)d_in[5];
    const float* b1  = (const float*)d_in[6];
    const float* W2  = (const float*)d_in[7];
    const float* b2  = (const float*)d_in[8];
    const float* Wm1 = (const float*)d_in[9];
    const float* bm1 = (const float*)d_in[10];
    const float* Wm2 = (const float*)d_in[11];
    const float* bm2 = (const float*)d_in[12];
    float* out = (float*)d_out;

    const int M = in_sizes[0] / 64;
    const int E = in_sizes[1] / 2;

    const int smem64  = 2 * 128 * (64  + 8) * 2 + 256;
    const int smem128 = 2 * 128 * (128 + 8) * 2 + 256;
    static float *pool_ptr = nullptr, *m1_ptr = nullptr;
    static cudaStream_t s1 = nullptr;
    static cudaEvent_t evA = nullptr, evB = nullptr;
    if (!pool_ptr) {
        cudaFuncSetAttribute(k_gemm_t<64,  false>, cudaFuncAttributeMaxDynamicSharedMemorySize, smem64);
        cudaFuncSetAttribute(k_gemm_t<128, true >, cudaFuncAttributeMaxDynamicSharedMemorySize, smem128);
        void* p;
        cudaGetSymbolAddress(&p, g_pool); pool_ptr = (float*)p;
        cudaGetSymbolAddress(&p, g_m1);   m1_ptr   = (float*)p;
        cudaStreamCreateWithFlags(&s1, cudaStreamNonBlocking);
        cudaEventCreateWithFlags(&evA, cudaEventDisableTiming);
        cudaEventCreateWithFlags(&evB, cudaEventDisableTiming);
    }

    const int TB = 256;
    int gbE1 = (E + TB - 1) / TB;          // 1 edge/thread (count)
    int gbE2 = (E / 2 + TB - 1) / TB;      // 2 edges/thread (fill)
    int gbS  = (M + SCAN_B - 1) / SCAN_B;
    int gbG  = NPAD / 128;
    int gbC  = (M + 7) / 8;

    // fork: prep chain on s1, layer-0 GEMM on main stream (independent)
    cudaEventRecord(evA, 0);
    cudaStreamWaitEvent(s1, evA, 0);
    k_count <<<gbE1, TB, 0, s1>>>(ei, E);          // 0  (g_cnt zeroed by prior scan23)
    k_scan1 <<<gbS, SCAN_B, 0, s1>>>(M);           // 1
    k_scan23<<<gbS, SCAN_B, 0, s1>>>(M, gbS);      // 2  (+ zero g_cnt)
    k_fill  <<<gbE2, TB, 0, s1>>>(ei, E);          // 3 <- ncu (regression guard)
    cudaEventRecord(evB, s1);

    k_gemm_t<64, false><<<gbG, TB, smem64>>>(x, W0, nullptr, M);   // ∥ prep
    cudaStreamWaitEvent(0, evB, 0);                                 // join

    k_conv  <<<gbC, TB>>>(M);
    k_gemm_t<128, true><<<gbG, TB, smem128>>>(nullptr, W1, b0, M);
    k_conv  <<<gbC, TB>>>(M);
    k_gemm_t<128, true><<<gbG, TB, smem128>>>(nullptr, W2, b1, M);
    k_conv  <<<gbC, TB>>>(M);

    k_pool<<<NOUT, 512>>>(batch, b2, M);
    dim3 gm1(NOUT / 16, NHID / 64);
    k_mlp_g<128, true ><<<gm1, TB>>>(pool_ptr, Wm1, bm1, m1_ptr, NHID);
    dim3 gm2(NOUT / 16, NOUT / 64);
    k_mlp_g<512, false><<<gm2, TB>>>(m1_ptr, Wm2, bm2, out, NOUT);
}